// round 12
// baseline (speedup 1.0000x reference)
#include <cuda_runtime.h>
#include <cuda_fp16.h>
#include <cstdint>
#include <cstddef>

#define BB 64
#define SS 512
#define DD 512
#define HH 512
#define GG 2048   // 4*HH

#define NBLK 128  // 32 hidden-groups x 4 batch-groups

// ---------------- scratch ----------------------------------------------------
__device__ float g_xg[(size_t)BB * SS * GG];   // [B,S,4H] input gates (bias folded)
__device__ unsigned g_flag[4][SS][32];         // per-(bg, step, block) ready flags

// ---------------- helpers -----------------------------------------------------
__device__ __forceinline__ uint32_t pack_h2(float lo, float hi) {
    __half2 h = __floats2half2_rn(lo, hi);
    return *(uint32_t*)&h;
}

__device__ __forceinline__ void mma_f16(float& c0, float& c1, float& c2, float& c3,
                                        uint32_t a0, uint32_t a1, uint32_t a2, uint32_t a3,
                                        uint32_t b0, uint32_t b1) {
    asm volatile(
        "mma.sync.aligned.m16n8k16.row.col.f32.f16.f16.f32 "
        "{%0,%1,%2,%3}, {%4,%5,%6,%7}, {%8,%9}, {%0,%1,%2,%3};"
        : "+f"(c0), "+f"(c1), "+f"(c2), "+f"(c3)
        : "r"(a0), "r"(a1), "r"(a2), "r"(a3), "r"(b0), "r"(b1));
}

__device__ __forceinline__ unsigned ld_acquire(const unsigned* p) {
    unsigned v;
    asm volatile("ld.global.acquire.gpu.u32 %0, [%1];" : "=r"(v) : "l"(p) : "memory");
    return v;
}
__device__ __forceinline__ void st_release(unsigned* p, unsigned v) {
    asm volatile("st.release.gpu.global.u32 [%0], %1;" :: "l"(p), "r"(v) : "memory");
}

// ---------------- kernel 1: xg = inputs @ W_ih^T + bias (mma f16) ------------
#define KC 32
#define ASTR2 20

__global__ __launch_bounds__(256) void xg_mma_kernel(
    const float* __restrict__ x, const float* __restrict__ emb,
    const float* __restrict__ W_ih, const float* __restrict__ b_ih,
    const float* __restrict__ b_hh)
{
    __shared__ uint32_t As[128 * ASTR2];
    __shared__ uint32_t Bs[128 * ASTR2];

    const int tid  = threadIdx.x;
    const int wid  = tid >> 5;
    const int lane = tid & 31;
    const int nBase = blockIdx.x * 128;
    const int mBase = blockIdx.y * 128;

    // zero the rec flags (stream-ordered before rec kernel)
    {
        int bid = blockIdx.y * gridDim.x + blockIdx.x;
        if (bid < 64) {
            unsigned* f = &g_flag[0][0][0];
            #pragma unroll
            for (int i = 0; i < 4; i++)
                f[bid * 1024 + i * 256 + tid] = 0u;
        }
    }

    const float* aSrc[4];
    const float* bSrc[4];
    int lRow[4], lQ[4];
    #pragma unroll
    for (int i = 0; i < 4; i++) {
        int slot = tid + i * 256;
        int r = slot >> 3;
        lRow[i] = r;
        lQ[i] = slot & 7;
        int m = mBase + r;
        int bidx = m >> 9, sidx = m & 511;
        aSrc[i] = (sidx == 0) ? (emb + (size_t)bidx * DD)
                              : (x + ((size_t)bidx * SS + (sidx - 1)) * DD);
        bSrc[i] = W_ih + (size_t)(nBase + r) * DD;
    }

    float acc[4][4][4];
    #pragma unroll
    for (int mf = 0; mf < 4; mf++)
        #pragma unroll
        for (int nf = 0; nf < 4; nf++)
            #pragma unroll
            for (int r = 0; r < 4; r++) acc[mf][nf][r] = 0.f;

    const int wm = (wid >> 2) * 64;
    const int wn = (wid & 3) * 32;
    const int lg = lane >> 2;
    const int lt = lane & 3;

    float4 pfA[4], pfB[4];
    #pragma unroll
    for (int i = 0; i < 4; i++) {
        pfA[i] = *(const float4*)(aSrc[i] + lQ[i] * 4);
        pfB[i] = *(const float4*)(bSrc[i] + lQ[i] * 4);
    }

    #pragma unroll 1
    for (int c = 0; c < DD / KC; c++) {
        #pragma unroll
        for (int i = 0; i < 4; i++) {
            uint32_t* pa = &As[lRow[i] * ASTR2 + lQ[i] * 2];
            uint32_t* pb = &Bs[lRow[i] * ASTR2 + lQ[i] * 2];
            pa[0] = pack_h2(pfA[i].x, pfA[i].y);
            pa[1] = pack_h2(pfA[i].z, pfA[i].w);
            pb[0] = pack_h2(pfB[i].x, pfB[i].y);
            pb[1] = pack_h2(pfB[i].z, pfB[i].w);
        }
        __syncthreads();

        if (c + 1 < DD / KC) {
            int ksrc = (c + 1) * KC;
            #pragma unroll
            for (int i = 0; i < 4; i++) {
                pfA[i] = *(const float4*)(aSrc[i] + ksrc + lQ[i] * 4);
                pfB[i] = *(const float4*)(bSrc[i] + ksrc + lQ[i] * 4);
            }
        }

        #pragma unroll
        for (int kk = 0; kk < KC / 16; kk++) {
            int kc = kk * 8;
            uint32_t a[4][4];
            #pragma unroll
            for (int mf = 0; mf < 4; mf++) {
                int r = wm + mf * 16 + lg;
                a[mf][0] = As[r * ASTR2 + kc + lt];
                a[mf][1] = As[(r + 8) * ASTR2 + kc + lt];
                a[mf][2] = As[r * ASTR2 + kc + 4 + lt];
                a[mf][3] = As[(r + 8) * ASTR2 + kc + 4 + lt];
            }
            uint32_t b[4][2];
            #pragma unroll
            for (int nf = 0; nf < 4; nf++) {
                int n = wn + nf * 8 + lg;
                b[nf][0] = Bs[n * ASTR2 + kc + lt];
                b[nf][1] = Bs[n * ASTR2 + kc + 4 + lt];
            }
            #pragma unroll
            for (int mf = 0; mf < 4; mf++)
                #pragma unroll
                for (int nf = 0; nf < 4; nf++)
                    mma_f16(acc[mf][nf][0], acc[mf][nf][1], acc[mf][nf][2], acc[mf][nf][3],
                            a[mf][0], a[mf][1], a[mf][2], a[mf][3],
                            b[nf][0], b[nf][1]);
        }
        __syncthreads();
    }

    #pragma unroll
    for (int nf = 0; nf < 4; nf++) {
        int n0 = nBase + wn + nf * 8 + 2 * lt;
        float bias0 = b_ih[n0] + b_hh[n0];
        float bias1 = b_ih[n0 + 1] + b_hh[n0 + 1];
        #pragma unroll
        for (int mf = 0; mf < 4; mf++) {
            int m0 = mBase + wm + mf * 16 + lg;
            float2 v0, v1;
            v0.x = acc[mf][nf][0] + bias0;
            v0.y = acc[mf][nf][1] + bias1;
            v1.x = acc[mf][nf][2] + bias0;
            v1.y = acc[mf][nf][3] + bias1;
            *(float2*)(g_xg + (size_t)m0 * GG + n0) = v0;
            *(float2*)(g_xg + (size_t)(m0 + 8) * GG + n0) = v1;
        }
    }
}

// ---------------- kernel 2: persistent LSTM recurrence (f16, flag barrier) ---
// 128 blocks = 32 hidden-groups (16 units) x 4 batch-groups (16 batches).
// 8 warps = (K-slice 0..3 of 128) x (batch-half 0..1).
// W_hh f16 fragments in registers; each warp stages only its own K-slice /
// batch-half of h, pair-syncs via named barrier. Flag-vector global barrier.
#define HSB 260                // hs row stride in uints (half2)
#define RED_NSTR 17
#define RED_KSTR (64 * RED_NSTR)

__global__ __launch_bounds__(256, 1) void lstm_rec_kernel(
    const float* __restrict__ h_n, const float* __restrict__ c_n,
    const float* __restrict__ W_hh, float* __restrict__ out)
{
    __shared__ uint32_t hs[16 * HSB];        // 16,640 B (half2 h stage)
    __shared__ float red[4 * RED_KSTR];      // 17,408 B

    const int tid = threadIdx.x;
    const int hg = blockIdx.x & 31;
    const int bg = blockIdx.x >> 5;
    const int j0 = hg * 16;
    const int b0 = bg * 16;

    const int wid  = tid >> 5;
    const int lane = tid & 31;
    const int lg = lane >> 2;
    const int lt = lane & 3;
    const int ksl = wid & 3;           // K slice: floats [ksl*128, +128)
    const int nh  = wid >> 2;          // row half: rows [nh*32, +32)
    const int kbase = ksl * 128;

    // -------- W_hh f16 fragments -> registers (once) -------------------------
    uint32_t Wf[4][8][2];
    #pragma unroll
    for (int nf = 0; nf < 4; nf++) {
        int nloc = nh * 32 + nf * 8 + lg;
        int grow = (nloc >> 4) * HH + j0 + (nloc & 15);
        const float* wr = W_hh + (size_t)grow * HH + kbase;
        #pragma unroll
        for (int kb = 0; kb < 8; kb++) {
            Wf[nf][kb][0] = pack_h2(wr[kb * 16 + 2 * lt],     wr[kb * 16 + 2 * lt + 1]);
            Wf[nf][kb][1] = pack_h2(wr[kb * 16 + 8 + 2 * lt], wr[kb * 16 + 8 + 2 * lt + 1]);
        }
    }

    const int jj_a = tid & 15;
    const int bb_a = tid >> 4;
    float creg = c_n[(size_t)(b0 + bb_a) * HH + j0 + jj_a];

    #pragma unroll 1
    for (int t = 0; t < SS; t++) {
        // xg prefetch (independent of barrier)
        size_t xb = ((size_t)(b0 + bb_a) * SS + t) * GG + j0 + jj_a;
        float xg0 = __ldcg(&g_xg[xb]);
        float xg1 = __ldcg(&g_xg[xb + HH]);
        float xg2 = __ldcg(&g_xg[xb + 2 * HH]);
        float xg3 = __ldcg(&g_xg[xb + 3 * HH]);

        // per-warp flag poll: 32 flags (one line) read by 32 lanes
        if (t > 0) {
            const unsigned* fp = &g_flag[bg][t - 1][lane];
            unsigned v = ld_acquire(fp);
            while (!__all_sync(0xFFFFFFFFu, v != 0u)) {
                v = ld_acquire(fp);
            }
        }

        // stage this warp's (batch-half, K-slice) of h_{t-1} as half2
        #pragma unroll
        for (int it = 0; it < 8; it++) {
            int bb = nh * 8 + it;
            const float* rp = (t == 0)
                ? (h_n + (size_t)(b0 + bb) * HH)
                : (out + ((size_t)(b0 + bb) * SS + (t - 1)) * HH);
            float4 v = __ldcg((const float4*)(rp + kbase + lane * 4));
            uint2 u;
            u.x = pack_h2(v.x, v.y);
            u.y = pack_h2(v.z, v.w);
            *(uint2*)(hs + bb * HSB + (kbase >> 1) + lane * 2) = u;
        }
        // pair barrier: warps {ksl, ksl+4} (64 threads) — both halves staged
        asm volatile("bar.sync %0, 64;" :: "r"(ksl + 1) : "memory");

        // mma over this warp's K slice (8 k-steps of 16), rows nh*32..+32
        float acc[4][4];
        #pragma unroll
        for (int nf = 0; nf < 4; nf++)
            #pragma unroll
            for (int r = 0; r < 4; r++) acc[nf][r] = 0.f;

        #pragma unroll
        for (int kb = 0; kb < 8; kb++) {
            int kc = (kbase >> 1) + kb * 8;
            uint32_t a0 = hs[lg * HSB + kc + lt];
            uint32_t a1 = hs[(8 + lg) * HSB + kc + lt];
            uint32_t a2 = hs[lg * HSB + kc + 4 + lt];
            uint32_t a3 = hs[(8 + lg) * HSB + kc + 4 + lt];
            #pragma unroll
            for (int nf = 0; nf < 4; nf++)
                mma_f16(acc[nf][0], acc[nf][1], acc[nf][2], acc[nf][3],
                        a0, a1, a2, a3, Wf[nf][kb][0], Wf[nf][kb][1]);
        }

        // partials -> red[ksl][row][m]
        {
            float* rbase = red + ksl * RED_KSTR;
            #pragma unroll
            for (int nf = 0; nf < 4; nf++) {
                int row0 = nh * 32 + nf * 8 + 2 * lt;
                rbase[row0 * RED_NSTR + lg]           = acc[nf][0];
                rbase[(row0 + 1) * RED_NSTR + lg]     = acc[nf][1];
                rbase[row0 * RED_NSTR + 8 + lg]       = acc[nf][2];
                rbase[(row0 + 1) * RED_NSTR + 8 + lg] = acc[nf][3];
            }
        }
        __syncthreads();

        // reduce 4 K-slices + LSTM elementwise (biases folded into xg)
        float s0 = 0.f, s1 = 0.f, s2 = 0.f, s3 = 0.f;
        #pragma unroll
        for (int ks2 = 0; ks2 < 4; ks2++) {
            const float* rp = red + ks2 * RED_KSTR;
            s0 += rp[(0 * 16 + jj_a) * RED_NSTR + bb_a];
            s1 += rp[(1 * 16 + jj_a) * RED_NSTR + bb_a];
            s2 += rp[(2 * 16 + jj_a) * RED_NSTR + bb_a];
            s3 += rp[(3 * 16 + jj_a) * RED_NSTR + bb_a];
        }
        float ig = __fdividef(1.f, 1.f + __expf(-(xg0 + s0)));
        float fg = __fdividef(1.f, 1.f + __expf(-(xg1 + s1)));
        float gc = tanhf(xg2 + s2);
        float og = __fdividef(1.f, 1.f + __expf(-(xg3 + s3)));
        creg = fg * creg + ig * gc;
        float hval = og * tanhf(creg);
        out[((size_t)(b0 + bb_a) * SS + t) * HH + j0 + jj_a] = hval;

        __syncthreads();   // all h stores of this block issued
        if (tid == 0) {
            st_release(&g_flag[bg][t][hg], 1u);
        }
    }
}

// ---------------- launch ------------------------------------------------------
extern "C" void kernel_launch(void* const* d_in, const int* in_sizes, int n_in,
                              void* d_out, int out_size)
{
    const float* x    = (const float*)d_in[0];
    const float* emb  = (const float*)d_in[1];
    const float* h_n  = (const float*)d_in[2];
    const float* c_n  = (const float*)d_in[3];
    const float* W_ih = (const float*)d_in[4];
    const float* W_hh = (const float*)d_in[5];
    const float* b_ih = (const float*)d_in[6];
    const float* b_hh = (const float*)d_in[7];
    float* out = (float*)d_out;

    xg_mma_kernel<<<dim3(GG / 128, (BB * SS) / 128), 256>>>(x, emb, W_ih, b_ih, b_hh);
    lstm_rec_kernel<<<NBLK, 256>>>(h_n, c_n, W_hh, out);
}

// round 13
// speedup vs baseline: 1.0915x; 1.0915x over previous
#include <cuda_runtime.h>
#include <cuda_fp16.h>
#include <cstdint>
#include <cstddef>

#define BB 64
#define SS 512
#define DD 512
#define HH 512

#define NBLK 128  // 32 hidden-groups x 4 batch-groups

// ---------------- scratch ----------------------------------------------------
__device__ unsigned int g_cnt[4 * SS];   // per-(batchgroup,step) arrivals

__global__ void zero_cnt_kernel() {
    int i = blockIdx.x * blockDim.x + threadIdx.x;
    if (i < 4 * SS) g_cnt[i] = 0u;
}

// ---------------- helpers -----------------------------------------------------
__device__ __forceinline__ uint32_t pack_h2(float lo, float hi) {
    __half2 h = __floats2half2_rn(lo, hi);
    return *(uint32_t*)&h;
}

__device__ __forceinline__ void mma_f16(float& c0, float& c1, float& c2, float& c3,
                                        uint32_t a0, uint32_t a1, uint32_t a2, uint32_t a3,
                                        uint32_t b0, uint32_t b1) {
    asm volatile(
        "mma.sync.aligned.m16n8k16.row.col.f32.f16.f16.f32 "
        "{%0,%1,%2,%3}, {%4,%5,%6,%7}, {%8,%9}, {%0,%1,%2,%3};"
        : "+f"(c0), "+f"(c1), "+f"(c2), "+f"(c3)
        : "r"(a0), "r"(a1), "r"(a2), "r"(a3), "r"(b0), "r"(b1));
}

// ---------------- fused persistent LSTM decoder (f16 mma) --------------------
// 128 blocks = 32 hidden-groups (16 units) x 4 batch-groups (16 batches).
// 8 warps = 8 K-slices of 64 (shared decomposition for D and H, both 512).
// gates[64 rows, 16 batches] = x_t @ Wih_slice^T + h_{t-1} @ Whh_slice^T.
//  - Whh f16 fragments: registers (64/thread, loaded once).
//  - Wih slice: smem half2 (66KB, loaded once).
//  - xg partials for step t+1: computed AFTER the step-t arrive, into the same
//    accumulator (just consumed) -> fills the inter-block slack, no extra regs.
//  - x staged per-warp (own K-slice x 16 batches) into its red sub-region.
#define WIS_STR 260            // Wis/hs row stride in uints (half2)
#define XW_STR 36              // per-warp x-stage row stride in uints
#define RED_NSTR 17
#define RED_KSTR (64 * RED_NSTR)
// smem words: Wis 64*260=16640 | hs 16*260=4160 | red 8*1088=8704  => 29504 w
#define SM_WIS 0
#define SM_HS  (64 * WIS_STR)
#define SM_RED (64 * WIS_STR + 16 * WIS_STR)
#define SM_TOTAL_W (64 * WIS_STR + 16 * WIS_STR + 8 * RED_KSTR)

__global__ __launch_bounds__(256, 1) void lstm_fused_kernel(
    const float* __restrict__ x, const float* __restrict__ emb,
    const float* __restrict__ h_n, const float* __restrict__ c_n,
    const float* __restrict__ W_ih, const float* __restrict__ W_hh,
    const float* __restrict__ b_ih, const float* __restrict__ b_hh,
    float* __restrict__ out)
{
    extern __shared__ uint32_t sm[];
    uint32_t* Wis = sm + SM_WIS;           // [64][260] half2 W_ih slice
    uint32_t* hs  = sm + SM_HS;            // [16][260] half2 h stage
    float* red    = (float*)(sm + SM_RED); // [8][1088] partials / x-stage

    const int tid = threadIdx.x;
    const int hg = blockIdx.x & 31;
    const int bg = blockIdx.x >> 5;
    const int j0 = hg * 16;
    const int b0 = bg * 16;

    const int wid  = tid >> 5;
    const int lane = tid & 31;
    const int lg = lane >> 2;
    const int lt = lane & 3;
    const int kbase = wid * 64;            // float k base of this warp's slice

    // -------- W_hh f16 fragments -> registers (once) -------------------------
    uint32_t Wf[8][4][2];
    #pragma unroll
    for (int nf = 0; nf < 8; nf++) {
        int nloc = nf * 8 + lg;
        int grow = (nloc >> 4) * HH + j0 + (nloc & 15);
        const float* wr = W_hh + (size_t)grow * HH + kbase;
        #pragma unroll
        for (int kb = 0; kb < 4; kb++) {
            Wf[nf][kb][0] = pack_h2(wr[kb * 16 + 2 * lt],     wr[kb * 16 + 2 * lt + 1]);
            Wf[nf][kb][1] = pack_h2(wr[kb * 16 + 8 + 2 * lt], wr[kb * 16 + 8 + 2 * lt + 1]);
        }
    }

    // -------- W_ih slice -> smem half2 (once) --------------------------------
    for (int idx = tid; idx < 64 * 128; idx += 256) {
        int r = idx >> 7;
        int q = (idx & 127) * 4;           // float col
        int grow = (r >> 4) * HH + j0 + (r & 15);
        float4 v = *(const float4*)(W_ih + (size_t)grow * DD + q);
        uint2 u;
        u.x = pack_h2(v.x, v.y);
        u.y = pack_h2(v.z, v.w);
        *(uint2*)(Wis + r * WIS_STR + (q >> 1)) = u;
    }

    // activation mapping + biases + c state
    const int jj_a = tid & 15;
    const int bb_a = tid >> 4;
    const float bias0 = b_ih[0 * HH + j0 + jj_a] + b_hh[0 * HH + j0 + jj_a];
    const float bias1 = b_ih[1 * HH + j0 + jj_a] + b_hh[1 * HH + j0 + jj_a];
    const float bias2 = b_ih[2 * HH + j0 + jj_a] + b_hh[2 * HH + j0 + jj_a];
    const float bias3 = b_ih[3 * HH + j0 + jj_a] + b_hh[3 * HH + j0 + jj_a];
    float creg = c_n[(size_t)(b0 + bb_a) * HH + j0 + jj_a];
    __syncthreads();   // Wis visible to all warps

    // per-warp x staging region (inside this warp's red slice) & lane mapping
    uint32_t* xw = (uint32_t*)(red + wid * RED_KSTR);
    const int xr = lane >> 1;   // batch row 0..15
    const int xh = lane & 1;    // k half (32 floats)

    // -------- prime acc with xg partials for t=0 (input = emb) ---------------
    float acc[8][4];
    {
        const float* rp = emb + (size_t)(b0 + xr) * DD + kbase + xh * 32;
        #pragma unroll
        for (int j = 0; j < 4; j++) {
            float4 v0 = *(const float4*)(rp + j * 8);
            float4 v1 = *(const float4*)(rp + j * 8 + 4);
            uint4 u;
            u.x = pack_h2(v0.x, v0.y); u.y = pack_h2(v0.z, v0.w);
            u.z = pack_h2(v1.x, v1.y); u.w = pack_h2(v1.z, v1.w);
            *(uint4*)(xw + xr * XW_STR + xh * 16 + j * 4) = u;
        }
        __syncwarp();

        #pragma unroll
        for (int nf = 0; nf < 8; nf++)
            #pragma unroll
            for (int r = 0; r < 4; r++) acc[nf][r] = 0.f;

        const int wk = kbase >> 1;   // uint col base in Wis
        #pragma unroll
        for (int kb = 0; kb < 4; kb++) {
            int kc = kb * 8;
            uint32_t a0 = xw[lg * XW_STR + kc + lt];
            uint32_t a1 = xw[(8 + lg) * XW_STR + kc + lt];
            uint32_t a2 = xw[lg * XW_STR + kc + 4 + lt];
            uint32_t a3 = xw[(8 + lg) * XW_STR + kc + 4 + lt];
            #pragma unroll
            for (int nf = 0; nf < 8; nf++) {
                uint32_t b0f = Wis[(nf * 8 + lg) * WIS_STR + wk + kc + lt];
                uint32_t b1f = Wis[(nf * 8 + lg) * WIS_STR + wk + kc + 4 + lt];
                mma_f16(acc[nf][0], acc[nf][1], acc[nf][2], acc[nf][3],
                        a0, a1, a2, a3, b0f, b1f);
            }
        }
    }

    unsigned* cnt_base = &g_cnt[bg * SS];

    #pragma unroll 1
    for (int t = 0; t < SS; t++) {
        // ---- barrier: h_{t-1} available ------------------------------------
        if (t > 0) {
            if (tid == 0) {
                volatile unsigned int* p = cnt_base + (t - 1);
                while (*p < 32u) { }
                __threadfence();
            }
        }
        __syncthreads();   // releases poll; also orders x-stage reads (prev iter) vs red writes below

        // ---- stage h_{t-1} as half2, coalesced, block-wide ------------------
        for (int idx = tid; idx < 16 * 128; idx += 256) {
            int bb = idx >> 7;
            int kq = (idx & 127) * 4;
            float4 v;
            if (t == 0)
                v = *(const float4*)(h_n + (size_t)(b0 + bb) * HH + kq);
            else
                v = __ldcg((const float4*)(out + ((size_t)(b0 + bb) * SS + (t - 1)) * HH + kq));
            uint2 u;
            u.x = pack_h2(v.x, v.y);
            u.y = pack_h2(v.z, v.w);
            *(uint2*)(hs + bb * WIS_STR + (kq >> 1)) = u;
        }
        __syncthreads();

        // ---- h-mma into acc (on top of xg partials) -------------------------
        #pragma unroll
        for (int kb = 0; kb < 4; kb++) {
            int kc = (kbase >> 1) + kb * 8;
            uint32_t a0 = hs[lg * WIS_STR + kc + lt];
            uint32_t a1 = hs[(8 + lg) * WIS_STR + kc + lt];
            uint32_t a2 = hs[lg * WIS_STR + kc + 4 + lt];
            uint32_t a3 = hs[(8 + lg) * WIS_STR + kc + 4 + lt];
            #pragma unroll
            for (int nf = 0; nf < 8; nf++)
                mma_f16(acc[nf][0], acc[nf][1], acc[nf][2], acc[nf][3],
                        a0, a1, a2, a3, Wf[nf][kb][0], Wf[nf][kb][1]);
        }

        // ---- partials -> red[ksl][n][m] -------------------------------------
        {
            float* rbase = red + wid * RED_KSTR;
            #pragma unroll
            for (int nf = 0; nf < 8; nf++) {
                int n0 = nf * 8 + 2 * lt;
                rbase[n0 * RED_NSTR + lg]           = acc[nf][0];
                rbase[(n0 + 1) * RED_NSTR + lg]     = acc[nf][1];
                rbase[n0 * RED_NSTR + 8 + lg]       = acc[nf][2];
                rbase[(n0 + 1) * RED_NSTR + 8 + lg] = acc[nf][3];
            }
        }
        __syncthreads();

        // ---- reduce + LSTM elementwise --------------------------------------
        float s0 = 0.f, s1 = 0.f, s2 = 0.f, s3 = 0.f;
        #pragma unroll
        for (int ks2 = 0; ks2 < 8; ks2++) {
            const float* rp = red + ks2 * RED_KSTR;
            s0 += rp[(0 * 16 + jj_a) * RED_NSTR + bb_a];
            s1 += rp[(1 * 16 + jj_a) * RED_NSTR + bb_a];
            s2 += rp[(2 * 16 + jj_a) * RED_NSTR + bb_a];
            s3 += rp[(3 * 16 + jj_a) * RED_NSTR + bb_a];
        }
        float ig = 1.f / (1.f + __expf(-(s0 + bias0)));
        float fg = 1.f / (1.f + __expf(-(s1 + bias1)));
        float gc = tanhf(s2 + bias2);
        float og = 1.f / (1.f + __expf(-(s3 + bias3)));
        creg = fg * creg + ig * gc;
        float hval = og * tanhf(creg);
        out[((size_t)(b0 + bb_a) * SS + t) * HH + j0 + jj_a] = hval;

        __syncthreads();   // h stores issued; red reads done (frees red for x-stage)
        if (tid == 0) {
            __threadfence();
            atomicAdd(cnt_base + t, 1u);
        }

        // ---- xg-mma for step t+1 (input x[:, t, :]) — fills barrier slack ---
        if (t < SS - 1) {
            const float* rp = x + ((size_t)(b0 + xr) * SS + t) * DD + kbase + xh * 32;
            #pragma unroll
            for (int j = 0; j < 4; j++) {
                float4 v0 = *(const float4*)(rp + j * 8);
                float4 v1 = *(const float4*)(rp + j * 8 + 4);
                uint4 u;
                u.x = pack_h2(v0.x, v0.y); u.y = pack_h2(v0.z, v0.w);
                u.z = pack_h2(v1.x, v1.y); u.w = pack_h2(v1.z, v1.w);
                *(uint4*)(xw + xr * XW_STR + xh * 16 + j * 4) = u;
            }
            __syncwarp();

            #pragma unroll
            for (int nf = 0; nf < 8; nf++)
                #pragma unroll
                for (int r = 0; r < 4; r++) acc[nf][r] = 0.f;

            const int wk = kbase >> 1;
            #pragma unroll
            for (int kb = 0; kb < 4; kb++) {
                int kc = kb * 8;
                uint32_t a0 = xw[lg * XW_STR + kc + lt];
                uint32_t a1 = xw[(8 + lg) * XW_STR + kc + lt];
                uint32_t a2 = xw[lg * XW_STR + kc + 4 + lt];
                uint32_t a3 = xw[(8 + lg) * XW_STR + kc + 4 + lt];
                #pragma unroll
                for (int nf = 0; nf < 8; nf++) {
                    uint32_t b0f = Wis[(nf * 8 + lg) * WIS_STR + wk + kc + lt];
                    uint32_t b1f = Wis[(nf * 8 + lg) * WIS_STR + wk + kc + 4 + lt];
                    mma_f16(acc[nf][0], acc[nf][1], acc[nf][2], acc[nf][3],
                            a0, a1, a2, a3, b0f, b1f);
                }
            }
        }
    }
}

// ---------------- launch ------------------------------------------------------
extern "C" void kernel_launch(void* const* d_in, const int* in_sizes, int n_in,
                              void* d_out, int out_size)
{
    const float* x    = (const float*)d_in[0];
    const float* emb  = (const float*)d_in[1];
    const float* h_n  = (const float*)d_in[2];
    const float* c_n  = (const float*)d_in[3];
    const float* W_ih = (const float*)d_in[4];
    const float* W_hh = (const float*)d_in[5];
    const float* b_ih = (const float*)d_in[6];
    const float* b_hh = (const float*)d_in[7];
    float* out = (float*)d_out;

    const int smemB = SM_TOTAL_W * (int)sizeof(uint32_t);   // 118,016 B
    cudaFuncSetAttribute(lstm_fused_kernel, cudaFuncAttributeMaxDynamicSharedMemorySize, smemB);

    zero_cnt_kernel<<<2, 1024>>>();
    lstm_fused_kernel<<<NBLK, 256, smemB>>>(x, emb, h_n, c_n, W_ih, W_hh, b_ih, b_hh, out);
}

// round 14
// speedup vs baseline: 1.1020x; 1.0096x over previous
#include <cuda_runtime.h>
#include <cuda_fp16.h>
#include <cstdint>
#include <cstddef>

#define BB 64
#define SS 512
#define DD 512
#define HH 512
#define GG 2048   // 4*HH

#define NBLK 128        // 32 hidden-groups x 4 batch-groups
#define ARRIVALS 256u   // 32 blocks x 8 warps per batch-group

// ---------------- scratch ----------------------------------------------------
__device__ float g_xg[(size_t)BB * SS * GG];   // [B,S,4H] input gates (bias folded)
__device__ unsigned int g_cnt[4 * SS];         // per-(batchgroup,step) arrivals

__global__ void zero_cnt_kernel() {
    int i = blockIdx.x * blockDim.x + threadIdx.x;
    if (i < 4 * SS) g_cnt[i] = 0u;
}

// ---------------- helpers -----------------------------------------------------
__device__ __forceinline__ uint32_t pack_h2(float lo, float hi) {
    __half2 h = __floats2half2_rn(lo, hi);
    return *(uint32_t*)&h;
}

__device__ __forceinline__ void mma_f16(float& c0, float& c1, float& c2, float& c3,
                                        uint32_t a0, uint32_t a1, uint32_t a2, uint32_t a3,
                                        uint32_t b0, uint32_t b1) {
    asm volatile(
        "mma.sync.aligned.m16n8k16.row.col.f32.f16.f16.f32 "
        "{%0,%1,%2,%3}, {%4,%5,%6,%7}, {%8,%9}, {%0,%1,%2,%3};"
        : "+f"(c0), "+f"(c1), "+f"(c2), "+f"(c3)
        : "r"(a0), "r"(a1), "r"(a2), "r"(a3), "r"(b0), "r"(b1));
}

// ---------------- kernel 1: xg = inputs @ W_ih^T + bias (mma f16) ------------
#define KC 32
#define ASTR2 20

__global__ __launch_bounds__(256) void xg_mma_kernel(
    const float* __restrict__ x, const float* __restrict__ emb,
    const float* __restrict__ W_ih, const float* __restrict__ b_ih,
    const float* __restrict__ b_hh)
{
    __shared__ uint32_t As[128 * ASTR2];
    __shared__ uint32_t Bs[128 * ASTR2];

    const int tid  = threadIdx.x;
    const int wid  = tid >> 5;
    const int lane = tid & 31;
    const int nBase = blockIdx.x * 128;
    const int mBase = blockIdx.y * 128;

    const float* aSrc[4];
    const float* bSrc[4];
    int lRow[4], lQ[4];
    #pragma unroll
    for (int i = 0; i < 4; i++) {
        int slot = tid + i * 256;
        int r = slot >> 3;
        lRow[i] = r;
        lQ[i] = slot & 7;
        int m = mBase + r;
        int bidx = m >> 9, sidx = m & 511;
        aSrc[i] = (sidx == 0) ? (emb + (size_t)bidx * DD)
                              : (x + ((size_t)bidx * SS + (sidx - 1)) * DD);
        bSrc[i] = W_ih + (size_t)(nBase + r) * DD;
    }

    float acc[4][4][4];
    #pragma unroll
    for (int mf = 0; mf < 4; mf++)
        #pragma unroll
        for (int nf = 0; nf < 4; nf++)
            #pragma unroll
            for (int r = 0; r < 4; r++) acc[mf][nf][r] = 0.f;

    const int wm = (wid >> 2) * 64;
    const int wn = (wid & 3) * 32;
    const int lg = lane >> 2;
    const int lt = lane & 3;

    float4 pfA[4], pfB[4];
    #pragma unroll
    for (int i = 0; i < 4; i++) {
        pfA[i] = __ldcg((const float4*)(aSrc[i] + lQ[i] * 4));
        pfB[i] = __ldcg((const float4*)(bSrc[i] + lQ[i] * 4));
    }

    #pragma unroll 1
    for (int c = 0; c < DD / KC; c++) {
        #pragma unroll
        for (int i = 0; i < 4; i++) {
            uint32_t* pa = &As[lRow[i] * ASTR2 + lQ[i] * 2];
            uint32_t* pb = &Bs[lRow[i] * ASTR2 + lQ[i] * 2];
            pa[0] = pack_h2(pfA[i].x, pfA[i].y);
            pa[1] = pack_h2(pfA[i].z, pfA[i].w);
            pb[0] = pack_h2(pfB[i].x, pfB[i].y);
            pb[1] = pack_h2(pfB[i].z, pfB[i].w);
        }
        __syncthreads();

        if (c + 1 < DD / KC) {
            int ksrc = (c + 1) * KC;
            #pragma unroll
            for (int i = 0; i < 4; i++) {
                pfA[i] = __ldcg((const float4*)(aSrc[i] + ksrc + lQ[i] * 4));
                pfB[i] = __ldcg((const float4*)(bSrc[i] + ksrc + lQ[i] * 4));
            }
        }

        #pragma unroll
        for (int kk = 0; kk < KC / 16; kk++) {
            int kc = kk * 8;
            uint32_t a[4][4];
            #pragma unroll
            for (int mf = 0; mf < 4; mf++) {
                int r = wm + mf * 16 + lg;
                a[mf][0] = As[r * ASTR2 + kc + lt];
                a[mf][1] = As[(r + 8) * ASTR2 + kc + lt];
                a[mf][2] = As[r * ASTR2 + kc + 4 + lt];
                a[mf][3] = As[(r + 8) * ASTR2 + kc + 4 + lt];
            }
            uint32_t b[4][2];
            #pragma unroll
            for (int nf = 0; nf < 4; nf++) {
                int n = wn + nf * 8 + lg;
                b[nf][0] = Bs[n * ASTR2 + kc + lt];
                b[nf][1] = Bs[n * ASTR2 + kc + 4 + lt];
            }
            #pragma unroll
            for (int mf = 0; mf < 4; mf++)
                #pragma unroll
                for (int nf = 0; nf < 4; nf++)
                    mma_f16(acc[mf][nf][0], acc[mf][nf][1], acc[mf][nf][2], acc[mf][nf][3],
                            a[mf][0], a[mf][1], a[mf][2], a[mf][3],
                            b[nf][0], b[nf][1]);
        }
        __syncthreads();
    }

    #pragma unroll
    for (int nf = 0; nf < 4; nf++) {
        int n0 = nBase + wn + nf * 8 + 2 * lt;
        float bias0 = b_ih[n0] + b_hh[n0];
        float bias1 = b_ih[n0 + 1] + b_hh[n0 + 1];
        #pragma unroll
        for (int mf = 0; mf < 4; mf++) {
            int m0 = mBase + wm + mf * 16 + lg;
            float2 v0, v1;
            v0.x = acc[mf][nf][0] + bias0;
            v0.y = acc[mf][nf][1] + bias1;
            v1.x = acc[mf][nf][2] + bias0;
            v1.y = acc[mf][nf][3] + bias1;
            *(float2*)(g_xg + (size_t)m0 * GG + n0) = v0;
            *(float2*)(g_xg + (size_t)(m0 + 8) * GG + n0) = v1;
        }
    }
}

// ---------------- kernel 2: persistent LSTM recurrence (f16 mma) -------------
// 128 blocks = 32 hidden-groups (16 units) x 4 batch-groups (16 batches).
// 8 warps = 8 K-slices of 64. W_hh f16 fragments in registers.
// PER-WARP h staging: warp w stages hs[all 16 batches][its own K-slice] and
// needs only __syncwarp before its mma. PER-WARP arrival (threshold 256).
// Block-wide __syncthreads: 2/step (poll release + red hazard).
#define HSB 260                // hs row stride in uints (half2)
#define RED_NSTR 17
#define RED_KSTR (64 * RED_NSTR)

__global__ __launch_bounds__(256, 1) void lstm_rec_kernel(
    const float* __restrict__ h_n, const float* __restrict__ c_n,
    const float* __restrict__ W_hh, float* __restrict__ out)
{
    __shared__ uint32_t hs[16 * HSB];       // 16,640 B
    __shared__ float red[8 * RED_KSTR];     // 34,816 B

    const int tid = threadIdx.x;
    const int hg = blockIdx.x & 31;
    const int bg = blockIdx.x >> 5;
    const int j0 = hg * 16;
    const int b0 = bg * 16;

    const int wid  = tid >> 5;
    const int lane = tid & 31;
    const int lg = lane >> 2;
    const int lt = lane & 3;
    const int kbase = wid * 64;        // float k base of this warp's slice

    // -------- W_hh f16 fragments -> registers (once) -------------------------
    uint32_t Wf[8][4][2];
    #pragma unroll
    for (int nf = 0; nf < 8; nf++) {
        int nloc = nf * 8 + lg;
        int grow = (nloc >> 4) * HH + j0 + (nloc & 15);
        const float* wr = W_hh + (size_t)grow * HH + kbase;
        #pragma unroll
        for (int kb = 0; kb < 4; kb++) {
            Wf[nf][kb][0] = pack_h2(wr[kb * 16 + 2 * lt],     wr[kb * 16 + 2 * lt + 1]);
            Wf[nf][kb][1] = pack_h2(wr[kb * 16 + 8 + 2 * lt], wr[kb * 16 + 8 + 2 * lt + 1]);
        }
    }

    const int jj_a = tid & 15;
    const int bb_a = tid >> 4;
    float creg = c_n[(size_t)(b0 + bb_a) * HH + j0 + jj_a];
    unsigned* cnt_base = &g_cnt[bg * SS];

    // per-warp stage mapping: 8 iters x (2 rows x 16 float4) covering
    // [16 batches] x [kbase, kbase+64)
    const int srow_off = lane >> 4;        // 0..1
    const int scol     = (lane & 15) * 4;  // float col within slice

    #pragma unroll 1
    for (int t = 0; t < SS; t++) {
        // xg prefetch (overlaps poll)
        size_t xb = ((size_t)(b0 + bb_a) * SS + t) * GG + j0 + jj_a;
        float xg0 = __ldcg(&g_xg[xb]);
        float xg1 = __ldcg(&g_xg[xb + HH]);
        float xg2 = __ldcg(&g_xg[xb + 2 * HH]);
        float xg3 = __ldcg(&g_xg[xb + 3 * HH]);

        // barrier: wait until all 256 warps of this bg arrived for step t-1
        if (t > 0) {
            if (tid == 0) {
                volatile unsigned int* p = cnt_base + (t - 1);
                while (*p < ARRIVALS) { }
                __threadfence();
            }
            __syncthreads();
        }

        // per-warp stage: 16 batches x own 64-float K-slice, as half2
        #pragma unroll
        for (int it = 0; it < 8; it++) {
            int bb = it * 2 + srow_off;
            const float* rp = (t == 0)
                ? (h_n + (size_t)(b0 + bb) * HH)
                : (out + ((size_t)(b0 + bb) * SS + (t - 1)) * HH);
            float4 v = __ldcg((const float4*)(rp + kbase + scol));
            uint2 u;
            u.x = pack_h2(v.x, v.y);
            u.y = pack_h2(v.z, v.w);
            *(uint2*)(hs + bb * HSB + ((kbase + scol) >> 1)) = u;
        }
        __syncwarp();

        // mma over this warp's K slice: 4 k-steps of 16
        float acc[8][4];
        #pragma unroll
        for (int nf = 0; nf < 8; nf++)
            #pragma unroll
            for (int r = 0; r < 4; r++) acc[nf][r] = 0.f;

        #pragma unroll
        for (int kb = 0; kb < 4; kb++) {
            int kc = (kbase >> 1) + kb * 8;
            uint32_t a0 = hs[lg * HSB + kc + lt];
            uint32_t a1 = hs[(8 + lg) * HSB + kc + lt];
            uint32_t a2 = hs[lg * HSB + kc + 4 + lt];
            uint32_t a3 = hs[(8 + lg) * HSB + kc + 4 + lt];
            #pragma unroll
            for (int nf = 0; nf < 8; nf++)
                mma_f16(acc[nf][0], acc[nf][1], acc[nf][2], acc[nf][3],
                        a0, a1, a2, a3, Wf[nf][kb][0], Wf[nf][kb][1]);
        }

        // partials -> red[ksl][n][m]
        {
            float* rbase = red + wid * RED_KSTR;
            #pragma unroll
            for (int nf = 0; nf < 8; nf++) {
                int n0 = nf * 8 + 2 * lt;
                rbase[n0 * RED_NSTR + lg]           = acc[nf][0];
                rbase[(n0 + 1) * RED_NSTR + lg]     = acc[nf][1];
                rbase[n0 * RED_NSTR + 8 + lg]       = acc[nf][2];
                rbase[(n0 + 1) * RED_NSTR + 8 + lg] = acc[nf][3];
            }
        }
        __syncthreads();

        // reduce + LSTM elementwise (biases folded into xg)
        float s0 = 0.f, s1 = 0.f, s2 = 0.f, s3 = 0.f;
        #pragma unroll
        for (int ks2 = 0; ks2 < 8; ks2++) {
            const float* rp = red + ks2 * RED_KSTR;
            s0 += rp[(0 * 16 + jj_a) * RED_NSTR + bb_a];
            s1 += rp[(1 * 16 + jj_a) * RED_NSTR + bb_a];
            s2 += rp[(2 * 16 + jj_a) * RED_NSTR + bb_a];
            s3 += rp[(3 * 16 + jj_a) * RED_NSTR + bb_a];
        }
        float ig = 1.f / (1.f + __expf(-(xg0 + s0)));
        float fg = 1.f / (1.f + __expf(-(xg1 + s1)));
        float gc = tanhf(xg2 + s2);
        float og = 1.f / (1.f + __expf(-(xg3 + s3)));
        creg = fg * creg + ig * gc;
        float hval = og * tanhf(creg);
        out[((size_t)(b0 + bb_a) * SS + t) * HH + j0 + jj_a] = hval;

        // per-warp arrival: this warp's h stores done
        __syncwarp();
        if (lane == 0) {
            __threadfence();
            atomicAdd(cnt_base + t, 1u);
        }
    }
}

// ---------------- launch ------------------------------------------------------
extern "C" void kernel_launch(void* const* d_in, const int* in_sizes, int n_in,
                              void* d_out, int out_size)
{
    const float* x    = (const float*)d_in[0];
    const float* emb  = (const float*)d_in[1];
    const float* h_n  = (const float*)d_in[2];
    const float* c_n  = (const float*)d_in[3];
    const float* W_ih = (const float*)d_in[4];
    const float* W_hh = (const float*)d_in[5];
    const float* b_ih = (const float*)d_in[6];
    const float* b_hh = (const float*)d_in[7];
    float* out = (float*)d_out;

    zero_cnt_kernel<<<2, 1024>>>();
    xg_mma_kernel<<<dim3(GG / 128, (BB * SS) / 128), 256>>>(x, emb, W_ih, b_ih, b_hh);
    lstm_rec_kernel<<<NBLK, 256>>>(h_n, c_n, W_hh, out);
}